// round 13
// baseline (speedup 1.0000x reference)
#include <cuda_runtime.h>
#include <cuda_fp16.h>
#include <cstdint>

#define N_NODES 100000
#define N_EDGES 1600000
#define F 128
#define NCLS 64
#define NCHUNK 4
#define CHSZ 25088            // multiple of 256 (gemm tile) and 8 (agg warps/block)

// ---------------- scratch (no allocation allowed; __device__ globals) ------
__device__ __half g_bufY[(size_t)N_NODES * F];    // Y0, then Y2 (fp16)
__device__ __half g_bufY2[(size_t)N_NODES * F];   // Y1 (fp16) — ping-pong partner
__device__ __half g_bufH[(size_t)N_NODES * F];    // h1 / h2 (fp16)
__device__ int    g_counts[N_NODES];
__device__ int    g_rowstart[N_NODES + 1];
__device__ int    g_cursor[N_NODES];
__device__ int    g_eidx[N_EDGES];
__device__ int    g_blocksums[128];

// ---------------- CSR build -----------------------------------------------
__global__ void k_hist(const int* __restrict__ dst) {
    int e = blockIdx.x * blockDim.x + threadIdx.x;
    if (e < N_EDGES) atomicAdd(&g_counts[dst[e]], 1);
}

__global__ void k_scan1() {
    __shared__ int s[1024];
    int t = threadIdx.x;
    int i = blockIdx.x * 1024 + t;
    int v = (i < N_NODES) ? g_counts[i] : 0;
    s[t] = v;
    __syncthreads();
    for (int off = 1; off < 1024; off <<= 1) {
        int x = (t >= off) ? s[t - off] : 0;
        __syncthreads();
        s[t] += x;
        __syncthreads();
    }
    if (i < N_NODES) g_rowstart[i] = s[t] - v;   // exclusive
    if (t == 1023) g_blocksums[blockIdx.x] = s[1023];
}

__global__ void k_scan2(int nblocks) {
    __shared__ int s[128];
    int t = threadIdx.x;
    int v = (t < nblocks) ? g_blocksums[t] : 0;
    s[t] = v;
    __syncthreads();
    for (int off = 1; off < 128; off <<= 1) {
        int x = (t >= off) ? s[t - off] : 0;
        __syncthreads();
        s[t] += x;
        __syncthreads();
    }
    if (t < nblocks) g_blocksums[t] = s[t] - v;  // exclusive
}

__global__ void k_scan3() {
    int i = blockIdx.x * blockDim.x + threadIdx.x;
    if (i < N_NODES) {
        int r = g_rowstart[i] + g_blocksums[i >> 10];
        g_rowstart[i] = r;
        g_cursor[i]   = r;
    }
    if (i == N_NODES) g_rowstart[N_NODES] = N_EDGES;
}

__global__ void k_scatter(const int* __restrict__ src, const int* __restrict__ dst) {
    int e = blockIdx.x * blockDim.x + threadIdx.x;
    if (e < N_EDGES) {
        int p = atomicAdd(&g_cursor[dst[e]], 1);
        g_eidx[p] = src[e];
    }
}

// ---------------- helpers --------------------------------------------------
__device__ __forceinline__ void acc_half4(float& ax, float& ay, float& az, float& aw,
                                          float2 r) {
    float2 a = __half22float2(*(__half2*)&r.x);
    float2 b = __half22float2(*(__half2*)&r.y);
    ax += a.x; ay += a.y; az += b.x; aw += b.y;
}

// ---------------- agg (fp16 Y, 128-wide) -> h fp16 (norm+bias+relu) -------
// Processes nodes [base, ...); warp per node.
__global__ void k_agg16_epi(const __half* __restrict__ Y16, const float* __restrict__ norm,
                            const float* __restrict__ bias, __half* __restrict__ out,
                            int base) {
    int w = base + ((blockIdx.x * blockDim.x + threadIdx.x) >> 5);
    int lane = threadIdx.x & 31;
    if (w >= N_NODES) return;
    int beg = g_rowstart[w];
    int end = g_rowstart[w + 1];

    float ax = 0.f, ay = 0.f, az = 0.f, aw = 0.f;
    int e = beg;
    for (; e + 8 <= end; e += 8) {
        int s0 = g_eidx[e + 0], s1 = g_eidx[e + 1];
        int s2 = g_eidx[e + 2], s3 = g_eidx[e + 3];
        int s4 = g_eidx[e + 4], s5 = g_eidx[e + 5];
        int s6 = g_eidx[e + 6], s7 = g_eidx[e + 7];
        float2 r0 = *(const float2*)(Y16 + (size_t)s0 * F + lane * 4);
        float2 r1 = *(const float2*)(Y16 + (size_t)s1 * F + lane * 4);
        float2 r2 = *(const float2*)(Y16 + (size_t)s2 * F + lane * 4);
        float2 r3 = *(const float2*)(Y16 + (size_t)s3 * F + lane * 4);
        float2 r4 = *(const float2*)(Y16 + (size_t)s4 * F + lane * 4);
        float2 r5 = *(const float2*)(Y16 + (size_t)s5 * F + lane * 4);
        float2 r6 = *(const float2*)(Y16 + (size_t)s6 * F + lane * 4);
        float2 r7 = *(const float2*)(Y16 + (size_t)s7 * F + lane * 4);
        acc_half4(ax, ay, az, aw, r0); acc_half4(ax, ay, az, aw, r1);
        acc_half4(ax, ay, az, aw, r2); acc_half4(ax, ay, az, aw, r3);
        acc_half4(ax, ay, az, aw, r4); acc_half4(ax, ay, az, aw, r5);
        acc_half4(ax, ay, az, aw, r6); acc_half4(ax, ay, az, aw, r7);
    }
    for (; e + 4 <= end; e += 4) {
        int s0 = g_eidx[e + 0], s1 = g_eidx[e + 1];
        int s2 = g_eidx[e + 2], s3 = g_eidx[e + 3];
        float2 r0 = *(const float2*)(Y16 + (size_t)s0 * F + lane * 4);
        float2 r1 = *(const float2*)(Y16 + (size_t)s1 * F + lane * 4);
        float2 r2 = *(const float2*)(Y16 + (size_t)s2 * F + lane * 4);
        float2 r3 = *(const float2*)(Y16 + (size_t)s3 * F + lane * 4);
        acc_half4(ax, ay, az, aw, r0); acc_half4(ax, ay, az, aw, r1);
        acc_half4(ax, ay, az, aw, r2); acc_half4(ax, ay, az, aw, r3);
    }
    for (; e < end; ++e) {
        int s = g_eidx[e];
        float2 r = *(const float2*)(Y16 + (size_t)s * F + lane * 4);
        acc_half4(ax, ay, az, aw, r);
    }
    float nf = norm[w];
    float4 b4 = *(const float4*)(bias + lane * 4);
    float hx = fmaxf(ax * nf + b4.x, 0.f);
    float hy = fmaxf(ay * nf + b4.y, 0.f);
    float hz = fmaxf(az * nf + b4.z, 0.f);
    float hw = fmaxf(aw * nf + b4.w, 0.f);
    __half2 p0 = __floats2half2_rn(hx, hy);
    __half2 p1 = __floats2half2_rn(hz, hw);
    float2 packed;
    *(__half2*)&packed.x = p0;
    *(__half2*)&packed.y = p1;
    *(float2*)(out + (size_t)w * F + lane * 4) = packed;
}

// ---------------- final agg (fp16 Y2, 64-wide) + norm + bias -> fp32 out --
__global__ void k_agg64_bias(const __half* __restrict__ Y16, const float* __restrict__ norm,
                             const float* __restrict__ bias, float* __restrict__ out) {
    int w = (blockIdx.x * blockDim.x + threadIdx.x) >> 5;
    int lane = threadIdx.x & 31;
    if (w >= N_NODES) return;
    int beg = g_rowstart[w];
    int end = g_rowstart[w + 1];

    float ax = 0.f, ay = 0.f;
    int e = beg;
    for (; e + 8 <= end; e += 8) {
        int s0 = g_eidx[e + 0], s1 = g_eidx[e + 1];
        int s2 = g_eidx[e + 2], s3 = g_eidx[e + 3];
        int s4 = g_eidx[e + 4], s5 = g_eidx[e + 5];
        int s6 = g_eidx[e + 6], s7 = g_eidx[e + 7];
        __half2 v0 = *(const __half2*)(Y16 + (size_t)s0 * NCLS + lane * 2);
        __half2 v1 = *(const __half2*)(Y16 + (size_t)s1 * NCLS + lane * 2);
        __half2 v2 = *(const __half2*)(Y16 + (size_t)s2 * NCLS + lane * 2);
        __half2 v3 = *(const __half2*)(Y16 + (size_t)s3 * NCLS + lane * 2);
        __half2 v4 = *(const __half2*)(Y16 + (size_t)s4 * NCLS + lane * 2);
        __half2 v5 = *(const __half2*)(Y16 + (size_t)s5 * NCLS + lane * 2);
        __half2 v6 = *(const __half2*)(Y16 + (size_t)s6 * NCLS + lane * 2);
        __half2 v7 = *(const __half2*)(Y16 + (size_t)s7 * NCLS + lane * 2);
        float2 f0 = __half22float2(v0), f1 = __half22float2(v1);
        float2 f2 = __half22float2(v2), f3 = __half22float2(v3);
        float2 f4 = __half22float2(v4), f5 = __half22float2(v5);
        float2 f6 = __half22float2(v6), f7 = __half22float2(v7);
        ax += f0.x + f1.x + f2.x + f3.x + f4.x + f5.x + f6.x + f7.x;
        ay += f0.y + f1.y + f2.y + f3.y + f4.y + f5.y + f6.y + f7.y;
    }
    for (; e + 4 <= end; e += 4) {
        int s0 = g_eidx[e + 0], s1 = g_eidx[e + 1];
        int s2 = g_eidx[e + 2], s3 = g_eidx[e + 3];
        __half2 v0 = *(const __half2*)(Y16 + (size_t)s0 * NCLS + lane * 2);
        __half2 v1 = *(const __half2*)(Y16 + (size_t)s1 * NCLS + lane * 2);
        __half2 v2 = *(const __half2*)(Y16 + (size_t)s2 * NCLS + lane * 2);
        __half2 v3 = *(const __half2*)(Y16 + (size_t)s3 * NCLS + lane * 2);
        float2 f0 = __half22float2(v0), f1 = __half22float2(v1);
        float2 f2 = __half22float2(v2), f3 = __half22float2(v3);
        ax += f0.x + f1.x + f2.x + f3.x;
        ay += f0.y + f1.y + f2.y + f3.y;
    }
    for (; e < end; ++e) {
        int s = g_eidx[e];
        float2 f = __half22float2(*(const __half2*)(Y16 + (size_t)s * NCLS + lane * 2));
        ax += f.x; ay += f.y;
    }
    float nf = norm[w];
    float2 b = *(const float2*)(bias + lane * 2);
    *(float2*)(out + (size_t)w * NCLS + lane * 2) = make_float2(ax * nf + b.x, ay * nf + b.y);
}

// ---------------- tf32 helpers --------------------------------------------
__device__ __forceinline__ uint32_t f2tf32(float f) {
    uint32_t u;
    asm("cvt.rna.tf32.f32 %0, %1;" : "=r"(u) : "f"(f));
    return u;
}

__device__ __forceinline__ void mma_tf32(float c[4],
                                         uint32_t a0, uint32_t a1, uint32_t a2, uint32_t a3,
                                         uint32_t b0, uint32_t b1) {
    asm volatile(
        "mma.sync.aligned.m16n8k8.row.col.f32.tf32.tf32.f32 "
        "{%0,%1,%2,%3}, {%4,%5,%6,%7}, {%8,%9}, {%0,%1,%2,%3};\n"
        : "+f"(c[0]), "+f"(c[1]), "+f"(c[2]), "+f"(c[3])
        : "r"(a0), "r"(a1), "r"(a2), "r"(a3), "r"(b0), "r"(b1));
}

// ---------------- GEMM: C(fp16) = A @ W; A fp32 or fp16; rows from base ---
template<int NOUT, bool HALF_IN>
__global__ void __launch_bounds__(512, 1)
k_gemm_tc(const void* __restrict__ Av, const float* __restrict__ W,
          __half* __restrict__ C16, int base) {
    constexpr int BM  = 256;
    constexpr int AST = 132;
    constexpr int WST = 136;
    constexpr int NTILES = NOUT / 32;

    extern __shared__ uint32_t sm[];
    uint32_t* As = sm;
    uint32_t* Ws = sm + BM * AST;

    int tid = threadIdx.x;
    int m0 = base + blockIdx.x * BM;

    for (int idx = tid * 4; idx < 128 * NOUT; idx += 512 * 4) {
        int k = idx / NOUT, n = idx % NOUT;
        float4 v = *(const float4*)&W[idx];
        uint32_t* p = &Ws[k * WST + n];
        p[0] = f2tf32(v.x); p[1] = f2tf32(v.y);
        p[2] = f2tf32(v.z); p[3] = f2tf32(v.w);
    }

    if (HALF_IN) {
        const __half* A16 = (const __half*)Av;
        for (int idx = tid; idx < BM * 16; idx += 512) {
            int m = idx >> 4, kq = idx & 15;
            float4 v = make_float4(0.f, 0.f, 0.f, 0.f);
            if (m0 + m < N_NODES)
                v = *(const float4*)(A16 + (size_t)(m0 + m) * 128 + kq * 8);
            const __half2* h2 = (const __half2*)&v;
            uint32_t* p = &As[m * AST + kq * 8];
#pragma unroll
            for (int j = 0; j < 4; ++j) {
                float2 f = __half22float2(h2[j]);
                p[2 * j]     = f2tf32(f.x);
                p[2 * j + 1] = f2tf32(f.y);
            }
        }
    } else {
        const float* A = (const float*)Av;
        for (int idx = tid; idx < BM * 32; idx += 512) {
            int m = idx >> 5, kq = idx & 31;
            float4 v = make_float4(0.f, 0.f, 0.f, 0.f);
            if (m0 + m < N_NODES)
                v = *(const float4*)&A[(size_t)(m0 + m) * 128 + kq * 4];
            uint32_t* p = &As[m * AST + kq * 4];
            p[0] = f2tf32(v.x); p[1] = f2tf32(v.y);
            p[2] = f2tf32(v.z); p[3] = f2tf32(v.w);
        }
    }
    __syncthreads();

    int wid  = tid >> 5, lane = tid & 31;
    int wm = wid & 3, wn = wid >> 2;
    int mbase = wm * 64;
    int nbase = wn * (NOUT / 4);
    int r = lane >> 2, c = lane & 3;

    float acc[4][NTILES][4];
#pragma unroll
    for (int mt = 0; mt < 4; ++mt)
#pragma unroll
        for (int nt = 0; nt < NTILES; ++nt)
#pragma unroll
            for (int i = 0; i < 4; ++i) acc[mt][nt][i] = 0.f;

#pragma unroll 2
    for (int k0 = 0; k0 < 128; k0 += 8) {
        uint32_t af[4][4];
#pragma unroll
        for (int mt = 0; mt < 4; ++mt) {
            int row = mbase + mt * 16 + r;
            af[mt][0] = As[row * AST + k0 + c];
            af[mt][1] = As[(row + 8) * AST + k0 + c];
            af[mt][2] = As[row * AST + k0 + c + 4];
            af[mt][3] = As[(row + 8) * AST + k0 + c + 4];
        }
        uint32_t bf[NTILES][2];
#pragma unroll
        for (int nt = 0; nt < NTILES; ++nt) {
            int col = nbase + nt * 8 + r;
            bf[nt][0] = Ws[(k0 + c) * WST + col];
            bf[nt][1] = Ws[(k0 + c + 4) * WST + col];
        }
#pragma unroll
        for (int mt = 0; mt < 4; ++mt)
#pragma unroll
            for (int nt = 0; nt < NTILES; ++nt)
                mma_tf32(acc[mt][nt], af[mt][0], af[mt][1], af[mt][2], af[mt][3],
                         bf[nt][0], bf[nt][1]);
    }

#pragma unroll
    for (int nt = 0; nt < NTILES; ++nt) {
        int col = nbase + nt * 8 + 2 * c;
#pragma unroll
        for (int mt = 0; mt < 4; ++mt) {
            int row = m0 + mbase + mt * 16 + r;
            if (row < N_NODES)
                *(__half2*)&C16[(size_t)row * NOUT + col] =
                    __floats2half2_rn(acc[mt][nt][0], acc[mt][nt][1]);
            if (row + 8 < N_NODES)
                *(__half2*)&C16[(size_t)(row + 8) * NOUT + col] =
                    __floats2half2_rn(acc[mt][nt][2], acc[mt][nt][3]);
        }
    }
}

// ---------------- launch ---------------------------------------------------
extern "C" void kernel_launch(void* const* d_in, const int* in_sizes, int n_in,
                              void* d_out, int out_size) {
    const float* features = (const float*)d_in[0];
    const float* norm     = (const float*)d_in[1];
    const float* W0       = (const float*)d_in[2];
    const float* b0       = (const float*)d_in[3];
    const float* W1       = (const float*)d_in[4];
    const float* b1       = (const float*)d_in[5];
    const float* W2       = (const float*)d_in[6];
    const float* b2       = (const float*)d_in[7];
    const int*   src      = (const int*)d_in[8];
    const int*   dst      = (const int*)d_in[9];
    float* out = (float*)d_out;

    __half *bufY = nullptr, *bufY2 = nullptr, *bufH = nullptr;
    int* countsPtr = nullptr;
    cudaGetSymbolAddress((void**)&bufY, g_bufY);
    cudaGetSymbolAddress((void**)&bufY2, g_bufY2);
    cudaGetSymbolAddress((void**)&bufH, g_bufH);
    cudaGetSymbolAddress((void**)&countsPtr, g_counts);

    const int SM_GEMM = (256 * 132 + 128 * 136) * 4;   // 204800 B
    cudaFuncSetAttribute(k_gemm_tc<128, false>, cudaFuncAttributeMaxDynamicSharedMemorySize, SM_GEMM);
    cudaFuncSetAttribute(k_gemm_tc<128, true >, cudaFuncAttributeMaxDynamicSharedMemorySize, SM_GEMM);
    cudaFuncSetAttribute(k_gemm_tc<64,  true >, cudaFuncAttributeMaxDynamicSharedMemorySize, SM_GEMM);

    static cudaStream_t s2 = nullptr;
    static cudaEvent_t evFork = nullptr, evG0 = nullptr, evG1 = nullptr, evG2 = nullptr;
    static cudaEvent_t evA0[NCHUNK], evA1[NCHUNK];
    if (!s2) {
        cudaStreamCreateWithFlags(&s2, cudaStreamNonBlocking);
        cudaEventCreateWithFlags(&evFork, cudaEventDisableTiming);
        cudaEventCreateWithFlags(&evG0, cudaEventDisableTiming);
        cudaEventCreateWithFlags(&evG1, cudaEventDisableTiming);
        cudaEventCreateWithFlags(&evG2, cudaEventDisableTiming);
        for (int i = 0; i < NCHUNK; ++i) {
            cudaEventCreateWithFlags(&evA0[i], cudaEventDisableTiming);
            cudaEventCreateWithFlags(&evA1[i], cudaEventDisableTiming);
        }
    }

    int gemmGridFull = (N_NODES + 255) / 256;       // 391

    // ---- fork: gemm0 (Y0 = feat @ W0 -> bufY fp16, independent of CSR) ----
    cudaEventRecord(evFork, 0);
    cudaStreamWaitEvent(s2, evFork, 0);
    k_gemm_tc<128, false><<<gemmGridFull, 512, SM_GEMM, s2>>>(features, W0, bufY, 0);
    cudaEventRecord(evG0, s2);

    // ---- CSR build (by dst), concurrent with gemm0 ----
    cudaMemsetAsync(countsPtr, 0, N_NODES * sizeof(int));
    k_hist<<<(N_EDGES + 255) / 256, 256>>>(dst);
    int nb = (N_NODES + 1023) / 1024;   // 98
    k_scan1<<<nb, 1024>>>();
    k_scan2<<<1, 128>>>(nb);
    k_scan3<<<(N_NODES + 1 + 255) / 256, 256>>>();
    k_scatter<<<(N_EDGES + 255) / 256, 256>>>(src, dst);

    cudaStreamWaitEvent(0, evG0, 0);   // Y0 ready before first gather

    // ---- boundary 0/1: chunked agg(bufY=Y0)->h1, gemm1 -> bufY2 (no alias) --
    for (int i = 0; i < NCHUNK; ++i) {
        int base = i * CHSZ;
        int cnt  = (base + CHSZ <= N_NODES) ? CHSZ : (N_NODES - base);
        k_agg16_epi<<<(cnt + 7) / 8, 256>>>(bufY, norm, b0, bufH, base);
        cudaEventRecord(evA0[i], 0);
        cudaStreamWaitEvent(s2, evA0[i], 0);
        k_gemm_tc<128, true><<<(cnt + 255) / 256, 512, SM_GEMM, s2>>>(bufH, W1, bufY2, base);
    }
    cudaEventRecord(evG1, s2);
    cudaStreamWaitEvent(0, evG1, 0);   // Y1 fully written before next gather

    // ---- boundary 1/2: chunked agg(bufY2=Y1)->h2, gemm64 -> bufY (no alias) --
    for (int i = 0; i < NCHUNK; ++i) {
        int base = i * CHSZ;
        int cnt  = (base + CHSZ <= N_NODES) ? CHSZ : (N_NODES - base);
        k_agg16_epi<<<(cnt + 7) / 8, 256>>>(bufY2, norm, b1, bufH, base);
        cudaEventRecord(evA1[i], 0);
        cudaStreamWaitEvent(s2, evA1[i], 0);
        k_gemm_tc<64, true><<<(cnt + 255) / 256, 512, SM_GEMM, s2>>>(bufH, W2, bufY, base);
    }
    cudaEventRecord(evG2, s2);
    cudaStreamWaitEvent(0, evG2, 0);   // Y2 fully written

    // ---- final: out = norm * segsum(Y2[src]) + b2 ----
    k_agg64_bias<<<(N_NODES + 7) / 8, 256>>>(bufY, norm, b2, out);
}

// round 15
// speedup vs baseline: 1.0955x; 1.0955x over previous
#include <cuda_runtime.h>
#include <cuda_fp16.h>
#include <cstdint>

#define N_NODES 100000
#define N_EDGES 1600000
#define F 128
#define NCLS 64

// ---------------- scratch (no allocation allowed; __device__ globals) ------
__device__ __half g_bufY[(size_t)N_NODES * F];    // Y0 / Y1 / Y2 (fp16)
__device__ __half g_bufH[(size_t)N_NODES * F];    // h1 / h2 (fp16)
__device__ int    g_counts[N_NODES];
__device__ int    g_rowstart[N_NODES + 1];
__device__ int    g_cursor[N_NODES];
__device__ int    g_eidx[N_EDGES];
__device__ int    g_blocksums[128];

// ---------------- CSR build -----------------------------------------------
__global__ void k_hist(const int* __restrict__ dst) {
    int e = blockIdx.x * blockDim.x + threadIdx.x;
    if (e < N_EDGES) atomicAdd(&g_counts[dst[e]], 1);
}

__global__ void k_scan1() {
    __shared__ int s[1024];
    int t = threadIdx.x;
    int i = blockIdx.x * 1024 + t;
    int v = (i < N_NODES) ? g_counts[i] : 0;
    s[t] = v;
    __syncthreads();
    for (int off = 1; off < 1024; off <<= 1) {
        int x = (t >= off) ? s[t - off] : 0;
        __syncthreads();
        s[t] += x;
        __syncthreads();
    }
    if (i < N_NODES) g_rowstart[i] = s[t] - v;   // exclusive
    if (t == 1023) g_blocksums[blockIdx.x] = s[1023];
}

__global__ void k_scan2(int nblocks) {
    __shared__ int s[128];
    int t = threadIdx.x;
    int v = (t < nblocks) ? g_blocksums[t] : 0;
    s[t] = v;
    __syncthreads();
    for (int off = 1; off < 128; off <<= 1) {
        int x = (t >= off) ? s[t - off] : 0;
        __syncthreads();
        s[t] += x;
        __syncthreads();
    }
    if (t < nblocks) g_blocksums[t] = s[t] - v;  // exclusive
}

__global__ void k_scan3() {
    int i = blockIdx.x * blockDim.x + threadIdx.x;
    if (i < N_NODES) {
        int r = g_rowstart[i] + g_blocksums[i >> 10];
        g_rowstart[i] = r;
        g_cursor[i]   = r;
    }
    if (i == N_NODES) g_rowstart[N_NODES] = N_EDGES;
}

__global__ void k_scatter(const int* __restrict__ src, const int* __restrict__ dst) {
    int e = blockIdx.x * blockDim.x + threadIdx.x;
    if (e < N_EDGES) {
        int p = atomicAdd(&g_cursor[dst[e]], 1);
        g_eidx[p] = src[e];
    }
}

// ---------------- agg (fp16 Y, 128-wide) -> h fp16 (norm+bias+relu) -------
// Warp per node; lane covers 4 halves (8 B). 8-edge fp16 HADD2 tree, fp32 top.
__global__ void k_agg16_epi(const __half* __restrict__ Y16, const float* __restrict__ norm,
                            const float* __restrict__ bias, __half* __restrict__ out) {
    int w = (blockIdx.x * blockDim.x + threadIdx.x) >> 5;
    int lane = threadIdx.x & 31;
    if (w >= N_NODES) return;
    int beg = g_rowstart[w];
    int end = g_rowstart[w + 1];

    float ax = 0.f, ay = 0.f, az = 0.f, aw = 0.f;
    int e = beg;
    for (; e + 8 <= end; e += 8) {
        int s0 = g_eidx[e + 0], s1 = g_eidx[e + 1];
        int s2 = g_eidx[e + 2], s3 = g_eidx[e + 3];
        int s4 = g_eidx[e + 4], s5 = g_eidx[e + 5];
        int s6 = g_eidx[e + 6], s7 = g_eidx[e + 7];
        float2 r0 = *(const float2*)(Y16 + (size_t)s0 * F + lane * 4);
        float2 r1 = *(const float2*)(Y16 + (size_t)s1 * F + lane * 4);
        float2 r2 = *(const float2*)(Y16 + (size_t)s2 * F + lane * 4);
        float2 r3 = *(const float2*)(Y16 + (size_t)s3 * F + lane * 4);
        float2 r4 = *(const float2*)(Y16 + (size_t)s4 * F + lane * 4);
        float2 r5 = *(const float2*)(Y16 + (size_t)s5 * F + lane * 4);
        float2 r6 = *(const float2*)(Y16 + (size_t)s6 * F + lane * 4);
        float2 r7 = *(const float2*)(Y16 + (size_t)s7 * F + lane * 4);
        // x-slot tree (halves 0,1)
        __half2 tx = __hadd2(__hadd2(__hadd2(*(__half2*)&r0.x, *(__half2*)&r1.x),
                                     __hadd2(*(__half2*)&r2.x, *(__half2*)&r3.x)),
                             __hadd2(__hadd2(*(__half2*)&r4.x, *(__half2*)&r5.x),
                                     __hadd2(*(__half2*)&r6.x, *(__half2*)&r7.x)));
        // y-slot tree (halves 2,3)
        __half2 ty = __hadd2(__hadd2(__hadd2(*(__half2*)&r0.y, *(__half2*)&r1.y),
                                     __hadd2(*(__half2*)&r2.y, *(__half2*)&r3.y)),
                             __hadd2(__hadd2(*(__half2*)&r4.y, *(__half2*)&r5.y),
                                     __hadd2(*(__half2*)&r6.y, *(__half2*)&r7.y)));
        float2 fx = __half22float2(tx);
        float2 fy = __half22float2(ty);
        ax += fx.x; ay += fx.y; az += fy.x; aw += fy.y;
    }
    for (; e + 4 <= end; e += 4) {
        int s0 = g_eidx[e + 0], s1 = g_eidx[e + 1];
        int s2 = g_eidx[e + 2], s3 = g_eidx[e + 3];
        float2 r0 = *(const float2*)(Y16 + (size_t)s0 * F + lane * 4);
        float2 r1 = *(const float2*)(Y16 + (size_t)s1 * F + lane * 4);
        float2 r2 = *(const float2*)(Y16 + (size_t)s2 * F + lane * 4);
        float2 r3 = *(const float2*)(Y16 + (size_t)s3 * F + lane * 4);
        __half2 tx = __hadd2(__hadd2(*(__half2*)&r0.x, *(__half2*)&r1.x),
                             __hadd2(*(__half2*)&r2.x, *(__half2*)&r3.x));
        __half2 ty = __hadd2(__hadd2(*(__half2*)&r0.y, *(__half2*)&r1.y),
                             __hadd2(*(__half2*)&r2.y, *(__half2*)&r3.y));
        float2 fx = __half22float2(tx);
        float2 fy = __half22float2(ty);
        ax += fx.x; ay += fx.y; az += fy.x; aw += fy.y;
    }
    for (; e < end; ++e) {
        int s = g_eidx[e];
        float2 r = *(const float2*)(Y16 + (size_t)s * F + lane * 4);
        float2 fx = __half22float2(*(__half2*)&r.x);
        float2 fy = __half22float2(*(__half2*)&r.y);
        ax += fx.x; ay += fx.y; az += fy.x; aw += fy.y;
    }
    float nf = norm[w];
    float4 b4 = *(const float4*)(bias + lane * 4);
    float hx = fmaxf(ax * nf + b4.x, 0.f);
    float hy = fmaxf(ay * nf + b4.y, 0.f);
    float hz = fmaxf(az * nf + b4.z, 0.f);
    float hw = fmaxf(aw * nf + b4.w, 0.f);
    __half2 p0 = __floats2half2_rn(hx, hy);
    __half2 p1 = __floats2half2_rn(hz, hw);
    float2 packed;
    *(__half2*)&packed.x = p0;
    *(__half2*)&packed.y = p1;
    *(float2*)(out + (size_t)w * F + lane * 4) = packed;
}

// ---------------- final agg (fp16 Y2, 64-wide) + norm + bias -> fp32 out --
__global__ void k_agg64_bias(const __half* __restrict__ Y16, const float* __restrict__ norm,
                             const float* __restrict__ bias, float* __restrict__ out) {
    int w = (blockIdx.x * blockDim.x + threadIdx.x) >> 5;
    int lane = threadIdx.x & 31;
    if (w >= N_NODES) return;
    int beg = g_rowstart[w];
    int end = g_rowstart[w + 1];

    float ax = 0.f, ay = 0.f;
    int e = beg;
    for (; e + 8 <= end; e += 8) {
        int s0 = g_eidx[e + 0], s1 = g_eidx[e + 1];
        int s2 = g_eidx[e + 2], s3 = g_eidx[e + 3];
        int s4 = g_eidx[e + 4], s5 = g_eidx[e + 5];
        int s6 = g_eidx[e + 6], s7 = g_eidx[e + 7];
        __half2 v0 = *(const __half2*)(Y16 + (size_t)s0 * NCLS + lane * 2);
        __half2 v1 = *(const __half2*)(Y16 + (size_t)s1 * NCLS + lane * 2);
        __half2 v2 = *(const __half2*)(Y16 + (size_t)s2 * NCLS + lane * 2);
        __half2 v3 = *(const __half2*)(Y16 + (size_t)s3 * NCLS + lane * 2);
        __half2 v4 = *(const __half2*)(Y16 + (size_t)s4 * NCLS + lane * 2);
        __half2 v5 = *(const __half2*)(Y16 + (size_t)s5 * NCLS + lane * 2);
        __half2 v6 = *(const __half2*)(Y16 + (size_t)s6 * NCLS + lane * 2);
        __half2 v7 = *(const __half2*)(Y16 + (size_t)s7 * NCLS + lane * 2);
        __half2 t = __hadd2(__hadd2(__hadd2(v0, v1), __hadd2(v2, v3)),
                            __hadd2(__hadd2(v4, v5), __hadd2(v6, v7)));
        float2 f = __half22float2(t);
        ax += f.x; ay += f.y;
    }
    for (; e + 4 <= end; e += 4) {
        int s0 = g_eidx[e + 0], s1 = g_eidx[e + 1];
        int s2 = g_eidx[e + 2], s3 = g_eidx[e + 3];
        __half2 v0 = *(const __half2*)(Y16 + (size_t)s0 * NCLS + lane * 2);
        __half2 v1 = *(const __half2*)(Y16 + (size_t)s1 * NCLS + lane * 2);
        __half2 v2 = *(const __half2*)(Y16 + (size_t)s2 * NCLS + lane * 2);
        __half2 v3 = *(const __half2*)(Y16 + (size_t)s3 * NCLS + lane * 2);
        __half2 t = __hadd2(__hadd2(v0, v1), __hadd2(v2, v3));
        float2 f = __half22float2(t);
        ax += f.x; ay += f.y;
    }
    for (; e < end; ++e) {
        int s = g_eidx[e];
        float2 f = __half22float2(*(const __half2*)(Y16 + (size_t)s * NCLS + lane * 2));
        ax += f.x; ay += f.y;
    }
    float nf = norm[w];
    float2 b = *(const float2*)(bias + lane * 2);
    *(float2*)(out + (size_t)w * NCLS + lane * 2) = make_float2(ax * nf + b.x, ay * nf + b.y);
}

// ---------------- tf32 helpers --------------------------------------------
__device__ __forceinline__ uint32_t f2tf32(float f) {
    uint32_t u;
    asm("cvt.rna.tf32.f32 %0, %1;" : "=r"(u) : "f"(f));
    return u;
}

__device__ __forceinline__ void mma_tf32(float c[4],
                                         uint32_t a0, uint32_t a1, uint32_t a2, uint32_t a3,
                                         uint32_t b0, uint32_t b1) {
    asm volatile(
        "mma.sync.aligned.m16n8k8.row.col.f32.tf32.tf32.f32 "
        "{%0,%1,%2,%3}, {%4,%5,%6,%7}, {%8,%9}, {%0,%1,%2,%3};\n"
        : "+f"(c[0]), "+f"(c[1]), "+f"(c[2]), "+f"(c[3])
        : "r"(a0), "r"(a1), "r"(a2), "r"(a3), "r"(b0), "r"(b1));
}

// ---------------- GEMM: C(fp16) = A @ W; A fp32 or fp16 -------------------
// BLOCK_M = 256 rows, 512 threads (16 warps), warp grid 4(m) x 4(n).
template<int NOUT, bool HALF_IN>
__global__ void __launch_bounds__(512, 1)
k_gemm_tc(const void* __restrict__ Av, const float* __restrict__ W,
          __half* __restrict__ C16) {
    constexpr int BM  = 256;
    constexpr int AST = 132;            // conflict-free A stride (words)
    constexpr int WST = 136;            // conflict-free W stride (words)
    constexpr int NTILES = NOUT / 32;

    extern __shared__ uint32_t sm[];
    uint32_t* As = sm;
    uint32_t* Ws = sm + BM * AST;

    int tid = threadIdx.x;
    int m0 = blockIdx.x * BM;

    for (int idx = tid * 4; idx < 128 * NOUT; idx += 512 * 4) {
        int k = idx / NOUT, n = idx % NOUT;
        float4 v = *(const float4*)&W[idx];
        uint32_t* p = &Ws[k * WST + n];
        p[0] = f2tf32(v.x); p[1] = f2tf32(v.y);
        p[2] = f2tf32(v.z); p[3] = f2tf32(v.w);
    }

    if (HALF_IN) {
        const __half* A16 = (const __half*)Av;
        for (int idx = tid; idx < BM * 16; idx += 512) {
            int m = idx >> 4, kq = idx & 15;
            float4 v = make_float4(0.f, 0.f, 0.f, 0.f);
            if (m0 + m < N_NODES)
                v = *(const float4*)(A16 + (size_t)(m0 + m) * 128 + kq * 8);
            const __half2* h2 = (const __half2*)&v;
            uint32_t* p = &As[m * AST + kq * 8];
#pragma unroll
            for (int j = 0; j < 4; ++j) {
                float2 f = __half22float2(h2[j]);
                p[2 * j]     = f2tf32(f.x);
                p[2 * j + 1] = f2tf32(f.y);
            }
        }
    } else {
        const float* A = (const float*)Av;
        for (int idx = tid; idx < BM * 32; idx += 512) {
            int m = idx >> 5, kq = idx & 31;
            float4 v = make_float4(0.f, 0.f, 0.f, 0.f);
            if (m0 + m < N_NODES)
                v = *(const float4*)&A[(size_t)(m0 + m) * 128 + kq * 4];
            uint32_t* p = &As[m * AST + kq * 4];
            p[0] = f2tf32(v.x); p[1] = f2tf32(v.y);
            p[2] = f2tf32(v.z); p[3] = f2tf32(v.w);
        }
    }
    __syncthreads();

    int wid  = tid >> 5, lane = tid & 31;
    int wm = wid & 3, wn = wid >> 2;
    int mbase = wm * 64;
    int nbase = wn * (NOUT / 4);
    int r = lane >> 2, c = lane & 3;

    float acc[4][NTILES][4];
#pragma unroll
    for (int mt = 0; mt < 4; ++mt)
#pragma unroll
        for (int nt = 0; nt < NTILES; ++nt)
#pragma unroll
            for (int i = 0; i < 4; ++i) acc[mt][nt][i] = 0.f;

#pragma unroll 2
    for (int k0 = 0; k0 < 128; k0 += 8) {
        uint32_t af[4][4];
#pragma unroll
        for (int mt = 0; mt < 4; ++mt) {
            int row = mbase + mt * 16 + r;
            af[mt][0] = As[row * AST + k0 + c];
            af[mt][1] = As[(row + 8) * AST + k0 + c];
            af[mt][2] = As[row * AST + k0 + c + 4];
            af[mt][3] = As[(row + 8) * AST + k0 + c + 4];
        }
        uint32_t bf[NTILES][2];
#pragma unroll
        for (int nt = 0; nt < NTILES; ++nt) {
            int col = nbase + nt * 8 + r;
            bf[nt][0] = Ws[(k0 + c) * WST + col];
            bf[nt][1] = Ws[(k0 + c + 4) * WST + col];
        }
#pragma unroll
        for (int mt = 0; mt < 4; ++mt)
#pragma unroll
            for (int nt = 0; nt < NTILES; ++nt)
                mma_tf32(acc[mt][nt], af[mt][0], af[mt][1], af[mt][2], af[mt][3],
                         bf[nt][0], bf[nt][1]);
    }

#pragma unroll
    for (int nt = 0; nt < NTILES; ++nt) {
        int col = nbase + nt * 8 + 2 * c;
#pragma unroll
        for (int mt = 0; mt < 4; ++mt) {
            int row = m0 + mbase + mt * 16 + r;
            if (row < N_NODES)
                *(__half2*)&C16[(size_t)row * NOUT + col] =
                    __floats2half2_rn(acc[mt][nt][0], acc[mt][nt][1]);
            if (row + 8 < N_NODES)
                *(__half2*)&C16[(size_t)(row + 8) * NOUT + col] =
                    __floats2half2_rn(acc[mt][nt][2], acc[mt][nt][3]);
        }
    }
}

// ---------------- launch ---------------------------------------------------
extern "C" void kernel_launch(void* const* d_in, const int* in_sizes, int n_in,
                              void* d_out, int out_size) {
    const float* features = (const float*)d_in[0];
    const float* norm     = (const float*)d_in[1];
    const float* W0       = (const float*)d_in[2];
    const float* b0       = (const float*)d_in[3];
    const float* W1       = (const float*)d_in[4];
    const float* b1       = (const float*)d_in[5];
    const float* W2       = (const float*)d_in[6];
    const float* b2       = (const float*)d_in[7];
    const int*   src      = (const int*)d_in[8];
    const int*   dst      = (const int*)d_in[9];
    float* out = (float*)d_out;

    __half *bufY = nullptr, *bufH = nullptr;
    int* countsPtr = nullptr;
    cudaGetSymbolAddress((void**)&bufY, g_bufY);
    cudaGetSymbolAddress((void**)&bufH, g_bufH);
    cudaGetSymbolAddress((void**)&countsPtr, g_counts);

    const int SM_GEMM = (256 * 132 + 128 * 136) * 4;   // 204800 B
    cudaFuncSetAttribute(k_gemm_tc<128, false>, cudaFuncAttributeMaxDynamicSharedMemorySize, SM_GEMM);
    cudaFuncSetAttribute(k_gemm_tc<128, true >, cudaFuncAttributeMaxDynamicSharedMemorySize, SM_GEMM);
    cudaFuncSetAttribute(k_gemm_tc<64,  true >, cudaFuncAttributeMaxDynamicSharedMemorySize, SM_GEMM);

    static cudaStream_t s2 = nullptr;
    static cudaEvent_t evFork = nullptr, evJoin = nullptr;
    if (!s2) {
        cudaStreamCreateWithFlags(&s2, cudaStreamNonBlocking);
        cudaEventCreateWithFlags(&evFork, cudaEventDisableTiming);
        cudaEventCreateWithFlags(&evJoin, cudaEventDisableTiming);
    }

    dim3 aggGrid((N_NODES + 7) / 8);            // warp per node
    int gemmGrid = (N_NODES + 255) / 256;       // 391

    // ---- fork: gemm0 (Y0 = feat @ W0 -> fp16, independent of CSR) on s2 ----
    cudaEventRecord(evFork, 0);
    cudaStreamWaitEvent(s2, evFork, 0);
    k_gemm_tc<128, false><<<gemmGrid, 512, SM_GEMM, s2>>>(features, W0, bufY);
    cudaEventRecord(evJoin, s2);

    // ---- CSR build (by dst), concurrent with gemm0 ----
    cudaMemsetAsync(countsPtr, 0, N_NODES * sizeof(int));
    k_hist<<<(N_EDGES + 255) / 256, 256>>>(dst);
    int nb = (N_NODES + 1023) / 1024;   // 98
    k_scan1<<<nb, 1024>>>();
    k_scan2<<<1, 128>>>(nb);
    k_scan3<<<(N_NODES + 1 + 255) / 256, 256>>>();
    k_scatter<<<(N_EDGES + 255) / 256, 256>>>(src, dst);

    cudaStreamWaitEvent(0, evJoin, 0);

    // layer 0 epilogue: h1 = relu(norm * segsum(Y0[src]) + b0)  (fp16 in/out)
    k_agg16_epi<<<aggGrid, 256>>>(bufY, norm, b0, bufH);
    // layer 1: Y1 = h1 @ W1 (fp16 A) ; h2 = relu(norm*segsum(Y1)+b1)
    k_gemm_tc<128, true><<<gemmGrid, 512, SM_GEMM>>>(bufH, W1, bufY);
    k_agg16_epi<<<aggGrid, 256>>>(bufY, norm, b1, bufH);
    // layer 2: Y2 = h2 @ W2 (fp16, 64-wide) ; out = norm*segsum(Y2)+b2 (fp32)
    k_gemm_tc<64, true><<<gemmGrid, 512, SM_GEMM>>>(bufH, W2, bufY);
    k_agg64_bias<<<aggGrid, 256>>>(bufY, norm, b2, out);
}

// round 16
// speedup vs baseline: 1.1117x; 1.0148x over previous
#include <cuda_runtime.h>
#include <cuda_fp16.h>
#include <cstdint>

#define N_NODES 100000
#define N_EDGES 1600000
#define F 128
#define NCLS 64

// ---------------- scratch (no allocation allowed; __device__ globals) ------
__device__ __half g_bufY[(size_t)N_NODES * F];    // Y0 / Y1 / Y2 (fp16)
__device__ __half g_bufH[(size_t)N_NODES * F];    // h1 / h2 (fp16)
__device__ int    g_counts[N_NODES];
__device__ int    g_rowstart[N_NODES + 1];
__device__ int    g_cursor[N_NODES];
__device__ int    g_eidx[N_EDGES];
__device__ int    g_blocksums[128];

// ---------------- CSR build -----------------------------------------------
__global__ void k_hist(const int* __restrict__ dst) {
    int e = blockIdx.x * blockDim.x + threadIdx.x;
    if (e < N_EDGES) atomicAdd(&g_counts[dst[e]], 1);
}

__global__ void k_scan1() {
    __shared__ int s[1024];
    int t = threadIdx.x;
    int i = blockIdx.x * 1024 + t;
    int v = (i < N_NODES) ? g_counts[i] : 0;
    s[t] = v;
    __syncthreads();
    for (int off = 1; off < 1024; off <<= 1) {
        int x = (t >= off) ? s[t - off] : 0;
        __syncthreads();
        s[t] += x;
        __syncthreads();
    }
    if (i < N_NODES) g_rowstart[i] = s[t] - v;   // exclusive
    if (t == 1023) g_blocksums[blockIdx.x] = s[1023];
}

__global__ void k_scan2(int nblocks) {
    __shared__ int s[128];
    int t = threadIdx.x;
    int v = (t < nblocks) ? g_blocksums[t] : 0;
    s[t] = v;
    __syncthreads();
    for (int off = 1; off < 128; off <<= 1) {
        int x = (t >= off) ? s[t - off] : 0;
        __syncthreads();
        s[t] += x;
        __syncthreads();
    }
    if (t < nblocks) g_blocksums[t] = s[t] - v;  // exclusive
}

__global__ void k_scan3() {
    int i = blockIdx.x * blockDim.x + threadIdx.x;
    if (i < N_NODES) {
        int r = g_rowstart[i] + g_blocksums[i >> 10];
        g_rowstart[i] = r;
        g_cursor[i]   = r;
    }
    if (i == N_NODES) g_rowstart[N_NODES] = N_EDGES;
}

__global__ void k_scatter(const int* __restrict__ src, const int* __restrict__ dst) {
    int e = blockIdx.x * blockDim.x + threadIdx.x;
    if (e < N_EDGES) {
        int p = atomicAdd(&g_cursor[dst[e]], 1);
        g_eidx[p] = src[e];
    }
}

// ---------------- agg (fp16 Y, 128-wide) -> h fp16 (norm+bias+relu) -------
// Warp per node; lane covers 4 halves (8 B). 8-edge fp16 HADD2 tree, fp32 top.
__global__ void k_agg16_epi(const __half* __restrict__ Y16, const float* __restrict__ norm,
                            const float* __restrict__ bias, __half* __restrict__ out) {
    int w = (blockIdx.x * blockDim.x + threadIdx.x) >> 5;
    int lane = threadIdx.x & 31;
    if (w >= N_NODES) return;
    int beg = g_rowstart[w];
    int end = g_rowstart[w + 1];

    float ax = 0.f, ay = 0.f, az = 0.f, aw = 0.f;
    int e = beg;
    for (; e + 8 <= end; e += 8) {
        int s0 = g_eidx[e + 0], s1 = g_eidx[e + 1];
        int s2 = g_eidx[e + 2], s3 = g_eidx[e + 3];
        int s4 = g_eidx[e + 4], s5 = g_eidx[e + 5];
        int s6 = g_eidx[e + 6], s7 = g_eidx[e + 7];
        float2 r0 = *(const float2*)(Y16 + (size_t)s0 * F + lane * 4);
        float2 r1 = *(const float2*)(Y16 + (size_t)s1 * F + lane * 4);
        float2 r2 = *(const float2*)(Y16 + (size_t)s2 * F + lane * 4);
        float2 r3 = *(const float2*)(Y16 + (size_t)s3 * F + lane * 4);
        float2 r4 = *(const float2*)(Y16 + (size_t)s4 * F + lane * 4);
        float2 r5 = *(const float2*)(Y16 + (size_t)s5 * F + lane * 4);
        float2 r6 = *(const float2*)(Y16 + (size_t)s6 * F + lane * 4);
        float2 r7 = *(const float2*)(Y16 + (size_t)s7 * F + lane * 4);
        __half2 tx = __hadd2(__hadd2(__hadd2(*(__half2*)&r0.x, *(__half2*)&r1.x),
                                     __hadd2(*(__half2*)&r2.x, *(__half2*)&r3.x)),
                             __hadd2(__hadd2(*(__half2*)&r4.x, *(__half2*)&r5.x),
                                     __hadd2(*(__half2*)&r6.x, *(__half2*)&r7.x)));
        __half2 ty = __hadd2(__hadd2(__hadd2(*(__half2*)&r0.y, *(__half2*)&r1.y),
                                     __hadd2(*(__half2*)&r2.y, *(__half2*)&r3.y)),
                             __hadd2(__hadd2(*(__half2*)&r4.y, *(__half2*)&r5.y),
                                     __hadd2(*(__half2*)&r6.y, *(__half2*)&r7.y)));
        float2 fx = __half22float2(tx);
        float2 fy = __half22float2(ty);
        ax += fx.x; ay += fx.y; az += fy.x; aw += fy.y;
    }
    for (; e + 4 <= end; e += 4) {
        int s0 = g_eidx[e + 0], s1 = g_eidx[e + 1];
        int s2 = g_eidx[e + 2], s3 = g_eidx[e + 3];
        float2 r0 = *(const float2*)(Y16 + (size_t)s0 * F + lane * 4);
        float2 r1 = *(const float2*)(Y16 + (size_t)s1 * F + lane * 4);
        float2 r2 = *(const float2*)(Y16 + (size_t)s2 * F + lane * 4);
        float2 r3 = *(const float2*)(Y16 + (size_t)s3 * F + lane * 4);
        __half2 tx = __hadd2(__hadd2(*(__half2*)&r0.x, *(__half2*)&r1.x),
                             __hadd2(*(__half2*)&r2.x, *(__half2*)&r3.x));
        __half2 ty = __hadd2(__hadd2(*(__half2*)&r0.y, *(__half2*)&r1.y),
                             __hadd2(*(__half2*)&r2.y, *(__half2*)&r3.y));
        float2 fx = __half22float2(tx);
        float2 fy = __half22float2(ty);
        ax += fx.x; ay += fx.y; az += fy.x; aw += fy.y;
    }
    for (; e < end; ++e) {
        int s = g_eidx[e];
        float2 r = *(const float2*)(Y16 + (size_t)s * F + lane * 4);
        float2 fx = __half22float2(*(__half2*)&r.x);
        float2 fy = __half22float2(*(__half2*)&r.y);
        ax += fx.x; ay += fx.y; az += fy.x; aw += fy.y;
    }
    float nf = norm[w];
    float4 b4 = *(const float4*)(bias + lane * 4);
    float hx = fmaxf(ax * nf + b4.x, 0.f);
    float hy = fmaxf(ay * nf + b4.y, 0.f);
    float hz = fmaxf(az * nf + b4.z, 0.f);
    float hw = fmaxf(aw * nf + b4.w, 0.f);
    __half2 p0 = __floats2half2_rn(hx, hy);
    __half2 p1 = __floats2half2_rn(hz, hw);
    float2 packed;
    *(__half2*)&packed.x = p0;
    *(__half2*)&packed.y = p1;
    *(float2*)(out + (size_t)w * F + lane * 4) = packed;
}

// ---------------- final agg (fp16 Y2, 64-wide) + norm + bias -> fp32 out --
__global__ void k_agg64_bias(const __half* __restrict__ Y16, const float* __restrict__ norm,
                             const float* __restrict__ bias, float* __restrict__ out) {
    int w = (blockIdx.x * blockDim.x + threadIdx.x) >> 5;
    int lane = threadIdx.x & 31;
    if (w >= N_NODES) return;
    int beg = g_rowstart[w];
    int end = g_rowstart[w + 1];

    float ax = 0.f, ay = 0.f;
    int e = beg;
    for (; e + 8 <= end; e += 8) {
        int s0 = g_eidx[e + 0], s1 = g_eidx[e + 1];
        int s2 = g_eidx[e + 2], s3 = g_eidx[e + 3];
        int s4 = g_eidx[e + 4], s5 = g_eidx[e + 5];
        int s6 = g_eidx[e + 6], s7 = g_eidx[e + 7];
        __half2 v0 = *(const __half2*)(Y16 + (size_t)s0 * NCLS + lane * 2);
        __half2 v1 = *(const __half2*)(Y16 + (size_t)s1 * NCLS + lane * 2);
        __half2 v2 = *(const __half2*)(Y16 + (size_t)s2 * NCLS + lane * 2);
        __half2 v3 = *(const __half2*)(Y16 + (size_t)s3 * NCLS + lane * 2);
        __half2 v4 = *(const __half2*)(Y16 + (size_t)s4 * NCLS + lane * 2);
        __half2 v5 = *(const __half2*)(Y16 + (size_t)s5 * NCLS + lane * 2);
        __half2 v6 = *(const __half2*)(Y16 + (size_t)s6 * NCLS + lane * 2);
        __half2 v7 = *(const __half2*)(Y16 + (size_t)s7 * NCLS + lane * 2);
        __half2 t = __hadd2(__hadd2(__hadd2(v0, v1), __hadd2(v2, v3)),
                            __hadd2(__hadd2(v4, v5), __hadd2(v6, v7)));
        float2 f = __half22float2(t);
        ax += f.x; ay += f.y;
    }
    for (; e + 4 <= end; e += 4) {
        int s0 = g_eidx[e + 0], s1 = g_eidx[e + 1];
        int s2 = g_eidx[e + 2], s3 = g_eidx[e + 3];
        __half2 v0 = *(const __half2*)(Y16 + (size_t)s0 * NCLS + lane * 2);
        __half2 v1 = *(const __half2*)(Y16 + (size_t)s1 * NCLS + lane * 2);
        __half2 v2 = *(const __half2*)(Y16 + (size_t)s2 * NCLS + lane * 2);
        __half2 v3 = *(const __half2*)(Y16 + (size_t)s3 * NCLS + lane * 2);
        __half2 t = __hadd2(__hadd2(v0, v1), __hadd2(v2, v3));
        float2 f = __half22float2(t);
        ax += f.x; ay += f.y;
    }
    for (; e < end; ++e) {
        int s = g_eidx[e];
        float2 f = __half22float2(*(const __half2*)(Y16 + (size_t)s * NCLS + lane * 2));
        ax += f.x; ay += f.y;
    }
    float nf = norm[w];
    float2 b = *(const float2*)(bias + lane * 2);
    *(float2*)(out + (size_t)w * NCLS + lane * 2) = make_float2(ax * nf + b.x, ay * nf + b.y);
}

// ---------------- fp16 MMA helper -----------------------------------------
__device__ __forceinline__ void mma_fp16(float c[4],
                                         uint32_t a0, uint32_t a1, uint32_t a2, uint32_t a3,
                                         uint32_t b0, uint32_t b1) {
    asm volatile(
        "mma.sync.aligned.m16n8k16.row.col.f32.f16.f16.f32 "
        "{%0,%1,%2,%3}, {%4,%5,%6,%7}, {%8,%9}, {%0,%1,%2,%3};\n"
        : "+f"(c[0]), "+f"(c[1]), "+f"(c[2]), "+f"(c[3])
        : "r"(a0), "r"(a1), "r"(a2), "r"(a3), "r"(b0), "r"(b1));
}

// ---------------- GEMM: C(fp16) = A @ W  via fp16 m16n8k16 ----------------
// BLOCK_M = 256 rows, 512 threads (16 warps), warp grid 4(m) x 4(n).
// As: [BM][AST] fp16 (k contiguous). Ws: [NOUT][WST] fp16 (k contiguous,
// i.e. W transposed). Stride 136 halves => word-bank = 4*row + t, conflict-free.
template<int NOUT, bool HALF_IN>
__global__ void __launch_bounds__(512, 1)
k_gemm_fp16(const void* __restrict__ Av, const float* __restrict__ W,
            __half* __restrict__ C16) {
    constexpr int BM  = 256;
    constexpr int AST = 136;            // halves
    constexpr int WST = 136;            // halves
    constexpr int NTILES = NOUT / 32;

    extern __shared__ __half smh[];
    __half* As = smh;                   // BM * AST
    __half* Ws = smh + BM * AST;        // NOUT * WST

    int tid = threadIdx.x;
    int m0 = blockIdx.x * BM;

    // W [k][NOUT] fp32 -> Ws[n][k] fp16 (transpose + convert)
    for (int idx = tid * 4; idx < 128 * NOUT; idx += 512 * 4) {
        int k = idx / NOUT, n = idx % NOUT;
        float4 v = *(const float4*)&W[idx];
        Ws[(n + 0) * WST + k] = __float2half_rn(v.x);
        Ws[(n + 1) * WST + k] = __float2half_rn(v.y);
        Ws[(n + 2) * WST + k] = __float2half_rn(v.z);
        Ws[(n + 3) * WST + k] = __float2half_rn(v.w);
    }

    // A tile -> As fp16
    if (HALF_IN) {
        const __half* A16 = (const __half*)Av;
        for (int idx = tid; idx < BM * 16; idx += 512) {
            int m = idx >> 4, kq = idx & 15;            // 8-half chunks
            float4 v = make_float4(0.f, 0.f, 0.f, 0.f);
            if (m0 + m < N_NODES)
                v = *(const float4*)(A16 + (size_t)(m0 + m) * 128 + kq * 8);
            *(float4*)&As[m * AST + kq * 8] = v;        // 16B aligned (AST even*2)
        }
    } else {
        const float* A = (const float*)Av;
        for (int idx = tid; idx < BM * 32; idx += 512) {
            int m = idx >> 5, kq = idx & 31;            // 4-float chunks
            float4 v = make_float4(0.f, 0.f, 0.f, 0.f);
            if (m0 + m < N_NODES)
                v = *(const float4*)&A[(size_t)(m0 + m) * 128 + kq * 4];
            __half2 h0 = __floats2half2_rn(v.x, v.y);
            __half2 h1 = __floats2half2_rn(v.z, v.w);
            uint2 pk = make_uint2(*(uint32_t*)&h0, *(uint32_t*)&h1);
            *(uint2*)&As[m * AST + kq * 4] = pk;        // 8B aligned
        }
    }
    __syncthreads();

    int wid  = tid >> 5, lane = tid & 31;
    int wm = wid & 3, wn = wid >> 2;
    int mbase = wm * 64;
    int nbase = wn * (NOUT / 4);
    int g = lane >> 2, t = lane & 3;

    float acc[4][NTILES][4];
#pragma unroll
    for (int mt = 0; mt < 4; ++mt)
#pragma unroll
        for (int nt = 0; nt < NTILES; ++nt)
#pragma unroll
            for (int i = 0; i < 4; ++i) acc[mt][nt][i] = 0.f;

#pragma unroll
    for (int k0 = 0; k0 < 128; k0 += 16) {
        uint32_t af[4][4];
#pragma unroll
        for (int mt = 0; mt < 4; ++mt) {
            int row = mbase + mt * 16 + g;
            af[mt][0] = *(const uint32_t*)&As[row * AST + k0 + 2 * t];
            af[mt][1] = *(const uint32_t*)&As[(row + 8) * AST + k0 + 2 * t];
            af[mt][2] = *(const uint32_t*)&As[row * AST + k0 + 2 * t + 8];
            af[mt][3] = *(const uint32_t*)&As[(row + 8) * AST + k0 + 2 * t + 8];
        }
        uint32_t bf[NTILES][2];
#pragma unroll
        for (int nt = 0; nt < NTILES; ++nt) {
            int col = nbase + nt * 8 + g;
            bf[nt][0] = *(const uint32_t*)&Ws[col * WST + k0 + 2 * t];
            bf[nt][1] = *(const uint32_t*)&Ws[col * WST + k0 + 2 * t + 8];
        }
#pragma unroll
        for (int mt = 0; mt < 4; ++mt)
#pragma unroll
            for (int nt = 0; nt < NTILES; ++nt)
                mma_fp16(acc[mt][nt], af[mt][0], af[mt][1], af[mt][2], af[mt][3],
                         bf[nt][0], bf[nt][1]);
    }

#pragma unroll
    for (int nt = 0; nt < NTILES; ++nt) {
        int col = nbase + nt * 8 + 2 * t;
#pragma unroll
        for (int mt = 0; mt < 4; ++mt) {
            int row = m0 + mbase + mt * 16 + g;
            if (row < N_NODES)
                *(__half2*)&C16[(size_t)row * NOUT + col] =
                    __floats2half2_rn(acc[mt][nt][0], acc[mt][nt][1]);
            if (row + 8 < N_NODES)
                *(__half2*)&C16[(size_t)(row + 8) * NOUT + col] =
                    __floats2half2_rn(acc[mt][nt][2], acc[mt][nt][3]);
        }
    }
}

// ---------------- launch ---------------------------------------------------
extern "C" void kernel_launch(void* const* d_in, const int* in_sizes, int n_in,
                              void* d_out, int out_size) {
    const float* features = (const float*)d_in[0];
    const float* norm     = (const float*)d_in[1];
    const float* W0       = (const float*)d_in[2];
    const float* b0       = (const float*)d_in[3];
    const float* W1       = (const float*)d_in[4];
    const float* b1       = (const float*)d_in[5];
    const float* W2       = (const float*)d_in[6];
    const float* b2       = (const float*)d_in[7];
    const int*   src      = (const int*)d_in[8];
    const int*   dst      = (const int*)d_in[9];
    float* out = (float*)d_out;

    __half *bufY = nullptr, *bufH = nullptr;
    int* countsPtr = nullptr;
    cudaGetSymbolAddress((void**)&bufY, g_bufY);
    cudaGetSymbolAddress((void**)&bufH, g_bufH);
    cudaGetSymbolAddress((void**)&countsPtr, g_counts);

    const int SM128 = (256 * 136 + 128 * 136) * 2;   // 104448 B
    const int SM64  = (256 * 136 + 64  * 136) * 2;   // 87040 B
    cudaFuncSetAttribute(k_gemm_fp16<128, false>, cudaFuncAttributeMaxDynamicSharedMemorySize, SM128);
    cudaFuncSetAttribute(k_gemm_fp16<128, true >, cudaFuncAttributeMaxDynamicSharedMemorySize, SM128);
    cudaFuncSetAttribute(k_gemm_fp16<64,  true >, cudaFuncAttributeMaxDynamicSharedMemorySize, SM64);

    static cudaStream_t s2 = nullptr;
    static cudaEvent_t evFork = nullptr, evJoin = nullptr;
    if (!s2) {
        cudaStreamCreateWithFlags(&s2, cudaStreamNonBlocking);
        cudaEventCreateWithFlags(&evFork, cudaEventDisableTiming);
        cudaEventCreateWithFlags(&evJoin, cudaEventDisableTiming);
    }

    dim3 aggGrid((N_NODES + 7) / 8);            // warp per node
    int gemmGrid = (N_NODES + 255) / 256;       // 391

    // ---- fork: gemm0 (Y0 = feat @ W0 -> fp16, independent of CSR) on s2 ----
    cudaEventRecord(evFork, 0);
    cudaStreamWaitEvent(s2, evFork, 0);
    k_gemm_fp16<128, false><<<gemmGrid, 512, SM128, s2>>>(features, W0, bufY);
    cudaEventRecord(evJoin, s2);

    // ---- CSR build (by dst), concurrent with gemm0 ----
    cudaMemsetAsync(countsPtr, 0, N_NODES * sizeof(int));
    k_hist<<<(N_EDGES + 255) / 256, 256>>>(dst);
    int nb = (N_NODES + 1023) / 1024;   // 98
    k_scan1<<<nb, 1024>>>();
    k_scan2<<<1, 128>>>(nb);
    k_scan3<<<(N_NODES + 1 + 255) / 256, 256>>>();
    k_scatter<<<(N_EDGES + 255) / 256, 256>>>(src, dst);

    cudaStreamWaitEvent(0, evJoin, 0);

    // layer 0 epilogue: h1 = relu(norm * segsum(Y0[src]) + b0)  (fp16 in/out)
    k_agg16_epi<<<aggGrid, 256>>>(bufY, norm, b0, bufH);
    // layer 1: Y1 = h1 @ W1 (fp16 MMA) ; h2 = relu(norm*segsum(Y1)+b1)
    k_gemm_fp16<128, true><<<gemmGrid, 512, SM128>>>(bufH, W1, bufY);
    k_agg16_epi<<<aggGrid, 256>>>(bufY, norm, b1, bufH);
    // layer 2: Y2 = h2 @ W2 (fp16, 64-wide) ; out = norm*segsum(Y2)+b2 (fp32)
    k_gemm_fp16<64, true><<<gemmGrid, 512, SM64>>>(bufH, W2, bufY);
    k_agg64_bias<<<aggGrid, 256>>>(bufY, norm, b2, out);
}